// round 5
// baseline (speedup 1.0000x reference)
#include <cuda_runtime.h>
#include <math.h>

#define B_ 32
#define T_ 512
#define D_ 512
#define P_ 200
#define NP_ 8
#define NEG_ (-100000.0f)

#define M_ (B_*T_)      // 16384
#define N_ (P_*NP_)     // 1600
#define K_ (D_)         // 512

// Scratch (allocation-free rule: __device__ globals)
__device__ float g_xn[M_*K_];      // normalized x, row-major [m][k]
__device__ float g_w[N_*K_];       // normalized prototypes [n=p*8+i][k=d]
__device__ float g_dist[M_*N_];    // [m][n], row pitch N_

// ---------------------------------------------------------------------------
// Normalize x rows: one block per (b,t) row of 512 floats
// ---------------------------------------------------------------------------
__global__ void norm_x_kernel(const float* __restrict__ x) {
    int row = blockIdx.x;
    const float4* xr = (const float4*)(x + (size_t)row * D_);
    float4 v = xr[threadIdx.x];  // 128 threads * 4 = 512
    float s = v.x*v.x + v.y*v.y + v.z*v.z + v.w*v.w;
    #pragma unroll
    for (int off = 16; off; off >>= 1) s += __shfl_down_sync(0xFFFFFFFFu, s, off);
    __shared__ float ws[4];
    int lane = threadIdx.x & 31, wid = threadIdx.x >> 5;
    if (lane == 0) ws[wid] = s;
    __syncthreads();
    float tot = ws[0] + ws[1] + ws[2] + ws[3];
    float nrm = fmaxf(sqrtf(tot), 1e-12f);
    float4 o = make_float4(v.x/nrm, v.y/nrm, v.z/nrm, v.w/nrm);
    ((float4*)g_xn)[(size_t)row * (D_/4) + threadIdx.x] = o;
}

// ---------------------------------------------------------------------------
// Normalize prototypes over D: one block per n = p*8+i
// proto layout (P, D, NP): proto[(p*D + d)*NP + i]
// ---------------------------------------------------------------------------
__global__ void norm_w_kernel(const float* __restrict__ proto) {
    int n = blockIdx.x;
    int p = n >> 3, i = n & 7;
    float vals[4];
    float s = 0.f;
    #pragma unroll
    for (int j = 0; j < 4; j++) {
        int d = threadIdx.x + j * 128;
        float v = proto[((size_t)p * D_ + d) * NP_ + i];
        vals[j] = v;
        s += v * v;
    }
    #pragma unroll
    for (int off = 16; off; off >>= 1) s += __shfl_down_sync(0xFFFFFFFFu, s, off);
    __shared__ float ws[4];
    int lane = threadIdx.x & 31, wid = threadIdx.x >> 5;
    if (lane == 0) ws[wid] = s;
    __syncthreads();
    float tot = ws[0] + ws[1] + ws[2] + ws[3];
    float nrm = fmaxf(sqrtf(tot), 1e-12f);
    #pragma unroll
    for (int j = 0; j < 4; j++) {
        int d = threadIdx.x + j * 128;
        g_w[(size_t)n * K_ + d] = vals[j] / nrm;
    }
}

// ---------------------------------------------------------------------------
// SGEMM: g_dist[m][n] = sum_k g_xn[m][k] * g_w[n][k]
// BM=128, BN=128, BK=8, 256 threads, 8x8 per-thread micro-tile
// ---------------------------------------------------------------------------
__global__ __launch_bounds__(256, 2) void sgemm_kernel() {
    __shared__ float As[8][128];
    __shared__ float Bs[8][128];
    const int tid = threadIdx.x;
    const int mBase = blockIdx.y * 128;
    const int nBase = blockIdx.x * 128;
    const int ty = tid >> 4, tx = tid & 15;
    const int loadRow = tid >> 1;
    const int loadK = (tid & 1) << 2;
    const int nIdx = nBase + loadRow;
    const bool bValid = (nIdx < N_);
    const float* aG = g_xn + (size_t)(mBase + loadRow) * K_ + loadK;
    const float* bG = bValid ? (g_w + (size_t)nIdx * K_ + loadK) : g_w;

    float acc[8][8];
    #pragma unroll
    for (int i = 0; i < 8; i++)
        #pragma unroll
        for (int j = 0; j < 8; j++) acc[i][j] = 0.f;

    for (int k0 = 0; k0 < K_; k0 += 8) {
        float4 a4 = *(const float4*)(aG + k0);
        float4 b4 = make_float4(0.f, 0.f, 0.f, 0.f);
        if (bValid) b4 = *(const float4*)(bG + k0);
        As[loadK + 0][loadRow] = a4.x;
        As[loadK + 1][loadRow] = a4.y;
        As[loadK + 2][loadRow] = a4.z;
        As[loadK + 3][loadRow] = a4.w;
        Bs[loadK + 0][loadRow] = b4.x;
        Bs[loadK + 1][loadRow] = b4.y;
        Bs[loadK + 2][loadRow] = b4.z;
        Bs[loadK + 3][loadRow] = b4.w;
        __syncthreads();
        #pragma unroll
        for (int kk = 0; kk < 8; kk++) {
            float4 a0 = *(const float4*)&As[kk][ty * 8];
            float4 a1 = *(const float4*)&As[kk][ty * 8 + 4];
            float4 b0 = *(const float4*)&Bs[kk][tx * 8];
            float4 b1 = *(const float4*)&Bs[kk][tx * 8 + 4];
            float ar[8] = {a0.x, a0.y, a0.z, a0.w, a1.x, a1.y, a1.z, a1.w};
            float br[8] = {b0.x, b0.y, b0.z, b0.w, b1.x, b1.y, b1.z, b1.w};
            #pragma unroll
            for (int i = 0; i < 8; i++)
                #pragma unroll
                for (int j = 0; j < 8; j++)
                    acc[i][j] = fmaf(ar[i], br[j], acc[i][j]);
        }
        __syncthreads();
    }

    const int n0 = nBase + tx * 8;
    if (n0 < N_) {  // N_ % 8 == 0, so a thread's 8 columns are all-or-nothing
        #pragma unroll
        for (int i = 0; i < 8; i++) {
            int m = mBase + ty * 8 + i;
            float* dst = g_dist + (size_t)m * N_ + n0;
            *(float4*)(dst + 0) = make_float4(acc[i][0], acc[i][1], acc[i][2], acc[i][3]);
            *(float4*)(dst + 4) = make_float4(acc[i][4], acc[i][5], acc[i][6], acc[i][7]);
        }
    }
}

// ---------------------------------------------------------------------------
// Selection: one block per (b, p). Replicates reference iterative argmax
// chain exactly, including first-index tie-breaking semantics.
// ---------------------------------------------------------------------------
__global__ __launch_bounds__(256) void select_kernel(
    const float* __restrict__ tmask,
    const float* __restrict__ psel,
    float* __restrict__ out)
{
    const int bp = blockIdx.x;
    const int b = bp / P_, p = bp % P_;
    const int tid = threadIdx.x;

    __shared__ float dist[T_][NP_ + 1];   // +1 pad: conflict-free column reads
    __shared__ float s_colv[NP_];
    __shared__ int   s_colt[NP_];
    __shared__ int   s_ev[NP_];
    __shared__ int   s_sub[NP_];
    __shared__ float s_val[NP_];
    __shared__ int   s_picked;
    __shared__ int   s_prev;
    __shared__ unsigned char s_tp[T_];    // t-picked flags

    // load tile, apply timeline mask: dist*tm + (1-tm)*NEG
    for (int t = tid; t < T_; t += 256) {
        float m = tmask[b * T_ + t];
        float c1 = 1.0f - m;
        const float4* src = (const float4*)(g_dist + ((size_t)(b * T_ + t)) * N_ + p * NP_);
        float4 v0 = src[0], v1 = src[1];
        dist[t][0] = v0.x * m + c1 * NEG_;
        dist[t][1] = v0.y * m + c1 * NEG_;
        dist[t][2] = v0.z * m + c1 * NEG_;
        dist[t][3] = v0.w * m + c1 * NEG_;
        dist[t][4] = v1.x * m + c1 * NEG_;
        dist[t][5] = v1.y * m + c1 * NEG_;
        dist[t][6] = v1.z * m + c1 * NEG_;
        dist[t][7] = v1.w * m + c1 * NEG_;
        s_tp[t] = 0;
        s_tp[t + 256 < T_ ? t : t] = s_tp[t]; // no-op keeps layout simple
    }
    if (tid == 0) { s_picked = 0; s_prev = 0; }
    __syncthreads();

    const int col = tid >> 5;      // 8 warps -> 8 subpatch columns
    const int lane = tid & 31;

    for (int it = 0; it < NP_; it++) {
        const bool colAvail = !((s_picked >> col) & 1);
        const int prev = s_prev;

        float bestv = 0.f; int bestt = 0; bool first = true;
        for (int t = lane; t < T_; t += 32) {
            bool avail = colAvail && (s_tp[t] == 0);
            if (it == 1) {
                int d = t - prev;
                avail = avail && (d >= -3) && (d <= 3);
            } else if (it >= 2) {
                int d = t - prev;
                avail = avail && (d >= 1) && (d <= 3);
            }
            float v = dist[t][col] + (avail ? 0.0f : NEG_);
            if (first || v > bestv || (v == bestv && t < bestt)) {
                bestv = v; bestt = t; first = false;
            }
        }
        // warp reduce: value desc, t asc on ties (first-index argmax semantics)
        #pragma unroll
        for (int off = 16; off; off >>= 1) {
            float ov = __shfl_down_sync(0xFFFFFFFFu, bestv, off);
            int   ot = __shfl_down_sync(0xFFFFFFFFu, bestt, off);
            if (ov > bestv || (ov == bestv && ot < bestt)) { bestv = ov; bestt = ot; }
        }
        if (lane == 0) { s_colv[col] = bestv; s_colt[col] = bestt; }
        __syncthreads();

        if (tid == 0) {
            float bv = s_colv[0]; int bi = 0;
            #pragma unroll
            for (int i = 1; i < NP_; i++)
                if (s_colv[i] > bv) { bv = s_colv[i]; bi = i; }  // strict > keeps first i
            int evt = s_colt[bi];
            s_ev[it] = evt;
            s_sub[it] = bi;
            s_val[it] = bv;
            s_picked |= (1 << bi);
            s_prev = evt;
            s_tp[evt] = 1;
        }
        __syncthreads();
    }

    if (tid == 0) {
        // stable argsort of sub ids (key = sub*8 + iteration index)
        int order[NP_]; bool used[NP_];
        #pragma unroll
        for (int j = 0; j < NP_; j++) used[j] = false;
        for (int pos = 0; pos < NP_; pos++) {
            int bk = -1, bkey = 1 << 30;
            for (int its = 0; its < NP_; its++) {
                if (!used[its]) {
                    int key = s_sub[its] * NP_ + its;
                    if (key < bkey) { bkey = key; bk = its; }
                }
            }
            used[bk] = true;
            order[pos] = bk;
        }
        // slots = sigmoid(patch_select); weight = slots * NP / (sum+1e-10)
        float slots[NP_], fsum = 0.f;
        #pragma unroll
        for (int j = 0; j < NP_; j++) {
            float s = 1.0f / (1.0f + expf(-psel[p * NP_ + j]));
            slots[j] = s; fsum += s;
        }
        fsum += 1e-10f;
        float ms = 0.f;
        #pragma unroll
        for (int j = 0; j < NP_; j++)
            ms += s_val[order[j]] * (slots[j] * (float)NP_ / fsum);

        out[bp] = ms;                      // max_activation_slots (B,P)
        out[B_ * P_ + bp] = (float)NP_ - ms;  // min_distances (B,P)
        float* idx_out = out + 2 * B_ * P_ + bp * NP_;
        #pragma unroll
        for (int j = 0; j < NP_; j++)
            idx_out[j] = (float)s_ev[order[j]];
    }
}

// ---------------------------------------------------------------------------
extern "C" void kernel_launch(void* const* d_in, const int* in_sizes, int n_in,
                              void* d_out, int out_size) {
    const float* x     = (const float*)d_in[0];  // (B,T,D)
    const float* tmask = (const float*)d_in[1];  // (B,T)
    const float* proto = (const float*)d_in[2];  // (P,D,NP)
    const float* psel  = (const float*)d_in[3];  // (1,P,NP)
    float* out = (float*)d_out;

    norm_x_kernel<<<M_, 128>>>(x);
    norm_w_kernel<<<N_, 128>>>(proto);
    dim3 g((N_ + 127) / 128, M_ / 128);   // (13, 128)
    sgemm_kernel<<<g, 256>>>();
    select_kernel<<<B_ * P_, 256>>>(tmask, psel, out);
}

// round 7
// speedup vs baseline: 1.9469x; 1.9469x over previous
#include <cuda_runtime.h>
#include <cuda_bf16.h>
#include <math.h>
#include <stdint.h>

#define B_ 32
#define T_ 512
#define D_ 512
#define P_ 200
#define NP_ 8
#define NEG_ (-100000.0f)

#define M_ (B_*T_)      // 16384
#define N_ (P_*NP_)     // 1600
#define NPAD_ 1664      // 13 * 128
#define K_ (D_)         // 512

// ---------------------------------------------------------------------------
// Scratch (__device__ globals; zero-initialized so W pad rows are zero)
// ---------------------------------------------------------------------------
__device__ __align__(16) __nv_bfloat16 g_xh[M_*K_];
__device__ __align__(16) __nv_bfloat16 g_xl[M_*K_];
__device__ __align__(16) __nv_bfloat16 g_xe[M_*K_];
__device__ __align__(16) __nv_bfloat16 g_wh[NPAD_*K_];
__device__ __align__(16) __nv_bfloat16 g_wl[NPAD_*K_];
__device__ __align__(16) __nv_bfloat16 g_we[NPAD_*K_];
__device__ __align__(16) float g_dist[M_*N_];   // [m][n], pitch N_

// ---------------------------------------------------------------------------
// Helpers
// ---------------------------------------------------------------------------
__device__ __forceinline__ uint32_t smem_to_u32(const void* p) {
    uint32_t a;
    asm("{ .reg .u64 t; cvta.to.shared.u64 t, %1; cvt.u32.u64 %0, t; }" : "=r"(a) : "l"(p));
    return a;
}
__device__ __forceinline__ void ldsm_x4(uint32_t* r, uint32_t addr) {
    asm volatile("ldmatrix.sync.aligned.m8n8.x4.shared.b16 {%0,%1,%2,%3}, [%4];"
        : "=r"(r[0]), "=r"(r[1]), "=r"(r[2]), "=r"(r[3]) : "r"(addr));
}
__device__ __forceinline__ void mma_bf16(float* c, const uint32_t* a, const uint32_t* b) {
    asm volatile(
        "mma.sync.aligned.m16n8k16.row.col.f32.bf16.bf16.f32 "
        "{%0,%1,%2,%3}, {%4,%5,%6,%7}, {%8,%9}, {%0,%1,%2,%3};"
        : "+f"(c[0]), "+f"(c[1]), "+f"(c[2]), "+f"(c[3])
        : "r"(a[0]), "r"(a[1]), "r"(a[2]), "r"(a[3]), "r"(b[0]), "r"(b[1]));
}
// Swizzled smem tile layout: 128 rows x 64B (4 x 16B chunks). Two rows per
// 128B line; chunk8 = (row&1)*4 + chunk, phys chunk8 ^= (line & 7).
// Conflict-free for ldmatrix over 8 consecutive rows at any fixed chunk.
__device__ __forceinline__ uint32_t swz(int row, int chunk) {
    return (uint32_t)(((row >> 1) * 128) +
           ((((((row & 1) << 2) | chunk)) ^ ((row >> 1) & 7)) << 4));
}

// ---------------------------------------------------------------------------
// Normalize + 3-way bf16 split of x rows
// ---------------------------------------------------------------------------
__global__ void norm_x_kernel(const float* __restrict__ x) {
    int row = blockIdx.x;
    const float4* xr = (const float4*)(x + (size_t)row * D_);
    float4 v = xr[threadIdx.x];
    float s = v.x*v.x + v.y*v.y + v.z*v.z + v.w*v.w;
    #pragma unroll
    for (int off = 16; off; off >>= 1) s += __shfl_down_sync(0xFFFFFFFFu, s, off);
    __shared__ float ws[4];
    int lane = threadIdx.x & 31, wid = threadIdx.x >> 5;
    if (lane == 0) ws[wid] = s;
    __syncthreads();
    float nrm = fmaxf(sqrtf(ws[0] + ws[1] + ws[2] + ws[3]), 1e-12f);
    float vals[4] = {v.x/nrm, v.y/nrm, v.z/nrm, v.w/nrm};
    size_t base = (size_t)row * K_ + threadIdx.x * 4;
    #pragma unroll
    for (int j = 0; j < 4; j++) {
        float f = vals[j];
        __nv_bfloat16 h = __float2bfloat16(f);
        float r1 = f - __bfloat162float(h);
        __nv_bfloat16 l = __float2bfloat16(r1);
        float r2 = r1 - __bfloat162float(l);
        __nv_bfloat16 e = __float2bfloat16(r2);
        g_xh[base + j] = h; g_xl[base + j] = l; g_xe[base + j] = e;
    }
}

// Normalize prototypes over D + split. One block per n = p*8+i.
__global__ void norm_w_kernel(const float* __restrict__ proto) {
    int n = blockIdx.x;
    int p = n >> 3, i = n & 7;
    float vals[4];
    float s = 0.f;
    #pragma unroll
    for (int j = 0; j < 4; j++) {
        int d = threadIdx.x + j * 128;
        float v = proto[((size_t)p * D_ + d) * NP_ + i];
        vals[j] = v; s += v * v;
    }
    #pragma unroll
    for (int off = 16; off; off >>= 1) s += __shfl_down_sync(0xFFFFFFFFu, s, off);
    __shared__ float ws[4];
    int lane = threadIdx.x & 31, wid = threadIdx.x >> 5;
    if (lane == 0) ws[wid] = s;
    __syncthreads();
    float nrm = fmaxf(sqrtf(ws[0] + ws[1] + ws[2] + ws[3]), 1e-12f);
    #pragma unroll
    for (int j = 0; j < 4; j++) {
        int d = threadIdx.x + j * 128;
        float f = vals[j] / nrm;
        __nv_bfloat16 h = __float2bfloat16(f);
        float r1 = f - __bfloat162float(h);
        __nv_bfloat16 l = __float2bfloat16(r1);
        float r2 = r1 - __bfloat162float(l);
        __nv_bfloat16 e = __float2bfloat16(r2);
        size_t idx = (size_t)n * K_ + d;
        g_wh[idx] = h; g_wl[idx] = l; g_we[idx] = e;
    }
}

// ---------------------------------------------------------------------------
// HMMA GEMM: dist = (xh+xl+xe)·(wh+wl+we), pairs {hh,hl,lh,ll,he,eh}
// BM=BN=128, BK=32, 256 threads, 8 warps (2x4), warp tile 64x32.
// ---------------------------------------------------------------------------
#define TILE_BYTES_ 8192
#define STAGE_BYTES_ (6*TILE_BYTES_)   // 49152
#define GEMM_SMEM (2*STAGE_BYTES_)     // 98304

__device__ __forceinline__ void load_chunk(int mBase, int nBase, int c, int stage,
                                           uint32_t smem_base, int tid) {
    const uint32_t sbase = smem_base + stage * STAGE_BYTES_;
    #pragma unroll
    for (int i = 0; i < 12; ++i) {
        int u = tid + i * 256;
        int t = u >> 9;            // tile 0..5 (512 x 16B per tile)
        int rem = u & 511;
        int row = rem >> 2;
        int chunk = rem & 3;
        const __nv_bfloat16* base;
        int rowg;
        if (t < 3) { base = (t == 0 ? g_xh : (t == 1 ? g_xl : g_xe)); rowg = mBase + row; }
        else       { base = (t == 3 ? g_wh : (t == 4 ? g_wl : g_we)); rowg = nBase + row; }
        const void* src = base + (size_t)rowg * K_ + c * 32 + chunk * 8;
        uint32_t dst = sbase + (uint32_t)t * TILE_BYTES_ + swz(row, chunk);
        asm volatile("cp.async.cg.shared.global [%0], [%1], 16;\n" :: "r"(dst), "l"(src));
    }
    asm volatile("cp.async.commit_group;\n" ::: "memory");
}

__global__ __launch_bounds__(256, 1) void gemm_kernel() {
    extern __shared__ char smem[];
    const uint32_t smem_base = smem_to_u32(smem);
    const int tid = threadIdx.x;
    const int wid = tid >> 5, lane = tid & 31;
    const int nBase = blockIdx.x * 128;
    const int mBase = blockIdx.y * 128;
    const int m_w = (wid & 1) * 64;   // warp row base
    const int n_w = (wid >> 1) * 32;  // warp col base

    float acc[4][4][4];
    #pragma unroll
    for (int i = 0; i < 4; i++)
        #pragma unroll
        for (int j = 0; j < 4; j++)
            #pragma unroll
            for (int q = 0; q < 4; q++) acc[i][j][q] = 0.f;

    load_chunk(mBase, nBase, 0, 0, smem_base, tid);

    // precomputed ldmatrix lane-address components
    const int a_row = m_w + (lane & 15);
    const int a_ch  = (lane >> 4);                 // 0 or 1 (k half)
    const int b_off = ((lane >> 4) << 3) + (lane & 7);  // row within n-tile pair
    const int b_ch  = ((lane >> 3) & 1);

    for (int c = 0; c < 16; ++c) {
        const int s = c & 1;
        if (c < 15) load_chunk(mBase, nBase, c + 1, s ^ 1, smem_base, tid);
        if (c < 15) asm volatile("cp.async.wait_group 1;\n" ::: "memory");
        else        asm volatile("cp.async.wait_group 0;\n" ::: "memory");
        __syncthreads();

        const uint32_t sb = smem_base + s * STAGE_BYTES_;
        #pragma unroll
        for (int ks = 0; ks < 2; ++ks) {
            uint32_t afr[3][4][4];
            #pragma unroll
            for (int ver = 0; ver < 3; ++ver)
                #pragma unroll
                for (int i = 0; i < 4; ++i) {
                    uint32_t addr = sb + ver * TILE_BYTES_ +
                                    swz(a_row + i * 16, 2 * ks + a_ch);
                    ldsm_x4(afr[ver][i], addr);
                }
            uint32_t bfr[3][4][2];
            #pragma unroll
            for (int ver = 0; ver < 3; ++ver)
                #pragma unroll
                for (int jp = 0; jp < 2; ++jp) {
                    uint32_t addr = sb + (3 + ver) * TILE_BYTES_ +
                                    swz(n_w + jp * 16 + b_off, 2 * ks + b_ch);
                    uint32_t r[4];
                    ldsm_x4(r, addr);
                    bfr[ver][jp*2  ][0] = r[0]; bfr[ver][jp*2  ][1] = r[1];
                    bfr[ver][jp*2+1][0] = r[2]; bfr[ver][jp*2+1][1] = r[3];
                }
            #pragma unroll
            for (int i = 0; i < 4; ++i)
                #pragma unroll
                for (int j = 0; j < 4; ++j) {
                    mma_bf16(acc[i][j], afr[0][i], bfr[0][j]);  // hh
                    mma_bf16(acc[i][j], afr[0][i], bfr[1][j]);  // hl
                    mma_bf16(acc[i][j], afr[1][i], bfr[0][j]);  // lh
                    mma_bf16(acc[i][j], afr[1][i], bfr[1][j]);  // ll
                    mma_bf16(acc[i][j], afr[0][i], bfr[2][j]);  // he
                    mma_bf16(acc[i][j], afr[2][i], bfr[0][j]);  // eh
                }
        }
        __syncthreads();
    }

    // Epilogue: direct store (float2 per row-group)
    #pragma unroll
    for (int i = 0; i < 4; ++i) {
        const int row = mBase + m_w + i * 16 + (lane >> 2);
        #pragma unroll
        for (int j = 0; j < 4; ++j) {
            const int ncol0 = nBase + n_w + j * 8;
            if (ncol0 < N_) {
                const int col = ncol0 + (lane & 3) * 2;
                *(float2*)(g_dist + (size_t)row * N_ + col) =
                    make_float2(acc[i][j][0], acc[i][j][1]);
                *(float2*)(g_dist + (size_t)(row + 8) * N_ + col) =
                    make_float2(acc[i][j][2], acc[i][j][3]);
            }
        }
    }
}

// ---------------------------------------------------------------------------
// Selection: one block per (b, p). Iteration 0: full scan, tracking BOTH the
// plain argmax (column value) and the argmax of fp32(dist+NEG) (rounded;
// NEG collapses ties at ulp(1e5)=0.0078 — the reference's fallback picks the
// FIRST t achieving the rounded max). Iterations 1..7: <=7-wide window scan.
// ---------------------------------------------------------------------------
__global__ __launch_bounds__(256) void select_kernel(
    const float* __restrict__ tmask,
    const float* __restrict__ psel,
    float* __restrict__ out)
{
    const int bp = blockIdx.x;
    const int b = bp / P_, p = bp % P_;
    const int tid = threadIdx.x;

    __shared__ float dist[T_][NP_ + 1];
    __shared__ float s_colv[NP_];
    __shared__ int   s_colt[NP_];
    __shared__ float s_grv[NP_];   // rounded fallback value
    __shared__ int   s_grt[NP_];   // rounded fallback t (first-tie)
    __shared__ int   s_ev[NP_];
    __shared__ int   s_sub[NP_];
    __shared__ float s_val[NP_];
    __shared__ int   s_picked;
    __shared__ int   s_prev;
    __shared__ unsigned char s_tp[T_];

    for (int t = tid; t < T_; t += 256) {
        float m = tmask[b * T_ + t];
        float c1 = 1.0f - m;
        const float4* src = (const float4*)(g_dist + ((size_t)(b * T_ + t)) * N_ + p * NP_);
        float4 v0 = src[0], v1 = src[1];
        dist[t][0] = v0.x * m + c1 * NEG_;
        dist[t][1] = v0.y * m + c1 * NEG_;
        dist[t][2] = v0.z * m + c1 * NEG_;
        dist[t][3] = v0.w * m + c1 * NEG_;
        dist[t][4] = v1.x * m + c1 * NEG_;
        dist[t][5] = v1.y * m + c1 * NEG_;
        dist[t][6] = v1.z * m + c1 * NEG_;
        dist[t][7] = v1.w * m + c1 * NEG_;
        s_tp[t] = 0;
    }
    if (tid == 0) { s_picked = 0; s_prev = 0; }
    __syncthreads();

    const int col = tid >> 5;
    const int lane = tid & 31;

    // ---- iteration 0 ----
    {
        float bv = dist[lane][col];            int bt = lane;
        float brv = __fadd_rn(bv, NEG_);       int brt = lane;
        #pragma unroll
        for (int j = 1; j < T_ / 32; j++) {
            int t = lane + j * 32;
            float v = dist[t][col];
            if (v > bv) { bv = v; bt = t; }               // ascending t: > keeps first
            float rv = __fadd_rn(v, NEG_);
            if (rv > brv) { brv = rv; brt = t; }
        }
        #pragma unroll
        for (int off = 16; off; off >>= 1) {
            float ov = __shfl_down_sync(0xFFFFFFFFu, bv, off);
            int   ot = __shfl_down_sync(0xFFFFFFFFu, bt, off);
            if (ov > bv || (ov == bv && ot < bt)) { bv = ov; bt = ot; }
            float orv = __shfl_down_sync(0xFFFFFFFFu, brv, off);
            int   ort = __shfl_down_sync(0xFFFFFFFFu, brt, off);
            if (orv > brv || (orv == brv && ort < brt)) { brv = orv; brt = ort; }
        }
        if (lane == 0) {
            s_colv[col] = bv;  s_colt[col] = bt;
            s_grv[col] = brv;  s_grt[col] = brt;
        }
        __syncthreads();
        if (tid == 0) {
            float v0 = s_colv[0]; int bi = 0;
            #pragma unroll
            for (int i = 1; i < NP_; i++)
                if (s_colv[i] > v0) { v0 = s_colv[i]; bi = i; }
            int evt = s_colt[bi];
            s_ev[0] = evt; s_sub[0] = bi; s_val[0] = v0;
            s_picked = (1 << bi);
            s_prev = evt;
            s_tp[evt] = 1;
        }
        __syncthreads();
    }

    // ---- iterations 1..7 ----
    for (int it = 1; it < NP_; it++) {
        const bool colAvail = !((s_picked >> col) & 1);
        const int prev = s_prev;

        float v = -INFINITY; int tt = 0x7FFFFFFF;
        if (colAvail && lane < 7) {
            int t; bool in;
            if (it == 1) { t = prev - 3 + lane; in = (t >= 0) && (t < T_); }
            else         { t = prev + 1 + lane; in = (lane < 3) && (t < T_); }
            if (in && s_tp[t] == 0) { v = dist[t][col]; tt = t; }
        }
        #pragma unroll
        for (int off = 4; off; off >>= 1) {
            float ov = __shfl_down_sync(0xFFFFFFFFu, v, off);
            int   ot = __shfl_down_sync(0xFFFFFFFFu, tt, off);
            if (ov > v || (ov == v && ot < tt)) { v = ov; tt = ot; }
        }
        if (lane == 0) {
            if (v == -INFINITY) { v = s_grv[col]; tt = s_grt[col]; }  // fallback
            s_colv[col] = v; s_colt[col] = tt;
        }
        __syncthreads();

        if (tid == 0) {
            float bv = s_colv[0]; int bi = 0;
            #pragma unroll
            for (int i = 1; i < NP_; i++)
                if (s_colv[i] > bv) { bv = s_colv[i]; bi = i; }
            int evt = s_colt[bi];
            s_ev[it] = evt; s_sub[it] = bi; s_val[it] = bv;
            s_picked |= (1 << bi);
            s_prev = evt;
            s_tp[evt] = 1;
        }
        __syncthreads();
    }

    if (tid == 0) {
        int order[NP_]; bool used[NP_];
        #pragma unroll
        for (int j = 0; j < NP_; j++) used[j] = false;
        for (int pos = 0; pos < NP_; pos++) {
            int bk = -1, bkey = 1 << 30;
            for (int its = 0; its < NP_; its++) {
                if (!used[its]) {
                    int key = s_sub[its] * NP_ + its;
                    if (key < bkey) { bkey = key; bk = its; }
                }
            }
            used[bk] = true;
            order[pos] = bk;
        }
        float slots[NP_], fsum = 0.f;
        #pragma unroll
        for (int j = 0; j < NP_; j++) {
            float s = 1.0f / (1.0f + expf(-psel[p * NP_ + j]));
            slots[j] = s; fsum += s;
        }
        fsum += 1e-10f;
        float ms = 0.f;
        #pragma unroll
        for (int j = 0; j < NP_; j++)
            ms += s_val[order[j]] * (slots[j] * (float)NP_ / fsum);

        out[bp] = ms;
        out[B_ * P_ + bp] = (float)NP_ - ms;
        float* idx_out = out + 2 * B_ * P_ + bp * NP_;
        #pragma unroll
        for (int j = 0; j < NP_; j++)
            idx_out[j] = (float)s_ev[order[j]];
    }
}

// ---------------------------------------------------------------------------
extern "C" void kernel_launch(void* const* d_in, const int* in_sizes, int n_in,
                              void* d_out, int out_size) {
    const float* x     = (const float*)d_in[0];  // (B,T,D)
    const float* tmask = (const float*)d_in[1];  // (B,T)
    const float* proto = (const float*)d_in[2];  // (P,D,NP)
    const float* psel  = (const float*)d_in[3];  // (1,P,NP)
    float* out = (float*)d_out;

    cudaFuncSetAttribute(gemm_kernel, cudaFuncAttributeMaxDynamicSharedMemorySize, GEMM_SMEM);

    norm_x_kernel<<<M_, 128>>>(x);
    norm_w_kernel<<<N_, 128>>>(proto);
    dim3 g(NPAD_ / 128, M_ / 128);   // (13, 128)
    gemm_kernel<<<g, 256, GEMM_SMEM>>>();
    select_kernel<<<B_ * P_, 256>>>(tmask, psel, out);
}